// round 2
// baseline (speedup 1.0000x reference)
#include <cuda_runtime.h>
#include <cuda_fp16.h>
#include <cstdint>

#define DEV __device__ __forceinline__
typedef unsigned long long u64;
typedef unsigned int u32;

static constexpr int NN = 50000;
static constexpr int EE = 800000;
static constexpr int D  = 64;

// ---------------- device scratch (no allocation allowed) ----------------
__device__ float g_esrc[(size_t)NN * D];
__device__ float g_edst[(size_t)NN * D];
__device__ float g_Bh  [(size_t)NN * D];
__device__ float g_xs  [(size_t)NN * D];
__device__ float g_num [(size_t)NN * D];
__device__ float g_den [(size_t)NN * D];
__device__ float g_xpre[(size_t)NN * D];
__device__ __half g_m  [(size_t)EE * D];
// stats: [0:64) e_sum [64:128) e_sumsq [128:192) n_sum [192:256) n_sumsq
__device__ float g_stat[256];
// bn params: [0:64) a_e [64:128) b_e [128:192) a_n [192:256) b_n
__device__ float g_bn[256];

// ---------------- helpers ----------------
DEV u64 pk2(float lo, float hi) {
    u64 r; asm("mov.b64 %0,{%1,%2};" : "=l"(r) : "f"(lo), "f"(hi)); return r;
}
DEV void upk2(u64 v, float& lo, float& hi) {
    asm("mov.b64 {%0,%1},%2;" : "=f"(lo), "=f"(hi) : "l"(v));
}
DEV void ffma2(u64& d, u64 a, u64 b) {
    asm("fma.rn.f32x2 %0,%1,%2,%0;" : "+l"(d) : "l"(a), "l"(b));
}
DEV void red4(float* p, float4 v) {
    asm volatile("red.global.add.v4.f32 [%0],{%1,%2,%3,%4};"
                 :: "l"(p), "f"(v.x), "f"(v.y), "f"(v.z), "f"(v.w) : "memory");
}
DEV float sigmoidf_(float v) { return __fdividef(1.f, 1.f + __expf(-v)); }
DEV float siluf_(float v)    { return __fdividef(v,   1.f + __expf(-v)); }

// ---------------- zero accumulators (every replay) ----------------
__global__ void k_zero() {
    int i = blockIdx.x * blockDim.x + threadIdx.x;   // grid covers NN*D exactly
    g_num[i] = 0.f;
    g_den[i] = 0.f;
    if (i < 256) g_stat[i] = 0.f;
}

// ---------------- 4 fused node GEMMs: esrc, edst, Bh, xs ----------------
// 128 threads, 128-node tile, each thread: 4 nodes x 16 features, f32x2 FMA.
__global__ __launch_bounds__(128) void k_node_gemm(
    const float* __restrict__ nf,
    const float* __restrict__ Wsg, const float* __restrict__ bsg,
    const float* __restrict__ Wdg, const float* __restrict__ bdg,
    const float* __restrict__ Wdu, const float* __restrict__ bdu,
    const float* __restrict__ Wsu, const float* __restrict__ bsu)
{
    extern __shared__ float sm[];
    float* W_sh  = sm;          // 4096 floats
    float* nf_sh = sm + 4096;   // 128*68 floats

    const int t = threadIdx.x;
    const int fg = t & 3, g = t >> 2;
    const int j0 = fg * 16;
    const int n0 = blockIdx.x * 128;

    // cooperative load of the node tile (padded stride 68 floats)
    {
        const float4* nfg = (const float4*)nf;
        #pragma unroll
        for (int i = 0; i < 16; i++) {
            int idx = t + i * 128;
            int row = idx >> 4, c4 = idx & 15;
            float4 v = (n0 + row < NN) ? nfg[(size_t)(n0 + row) * 16 + c4]
                                       : make_float4(0.f, 0.f, 0.f, 0.f);
            ((float4*)(nf_sh + row * 68))[c4] = v;
        }
    }

    const float* Wp[4] = {Wsg, Wdg, Wdu, Wsu};
    const float* bp[4] = {bsg, bdg, bdu, bsu};
    float*       op[4] = {g_esrc, g_edst, g_Bh, g_xs};

    #pragma unroll
    for (int mi = 0; mi < 4; mi++) {
        __syncthreads();
        {   // load W for this matrix
            float4* Wd = (float4*)W_sh;
            const float4* Wg = (const float4*)Wp[mi];
            #pragma unroll
            for (int i = 0; i < 8; i++) Wd[t + i * 128] = Wg[t + i * 128];
        }
        __syncthreads();

        u64 acc[4][8];
        {
            const float4* bg4 = (const float4*)(bp[mi] + j0);
            float4 b0 = bg4[0], b1 = bg4[1], b2 = bg4[2], b3 = bg4[3];
            u64 bb[8] = {pk2(b0.x,b0.y), pk2(b0.z,b0.w), pk2(b1.x,b1.y), pk2(b1.z,b1.w),
                         pk2(b2.x,b2.y), pk2(b2.z,b2.w), pk2(b3.x,b3.y), pk2(b3.z,b3.w)};
            #pragma unroll
            for (int q = 0; q < 4; q++)
                #pragma unroll
                for (int i = 0; i < 8; i++) acc[q][i] = bb[i];
        }

        const u64* W2 = (const u64*)W_sh;
        #pragma unroll 4
        for (int k = 0; k < 64; k++) {
            u64 w[8];
            #pragma unroll
            for (int i = 0; i < 8; i++) w[i] = W2[k * 32 + (j0 >> 1) + i];
            #pragma unroll
            for (int q = 0; q < 4; q++) {
                float ev = nf_sh[(g + 32 * q) * 68 + k];
                u64 e2 = pk2(ev, ev);
                #pragma unroll
                for (int i = 0; i < 8; i++) ffma2(acc[q][i], e2, w[i]);
            }
        }

        #pragma unroll
        for (int q = 0; q < 4; q++) {
            int n = n0 + g + 32 * q;
            if (n < NN) {
                float o[16];
                #pragma unroll
                for (int i = 0; i < 8; i++) upk2(acc[q][i], o[2 * i], o[2 * i + 1]);
                float4* dst4 = (float4*)(op[mi] + (size_t)n * 64 + j0);
                #pragma unroll
                for (int ii = 0; ii < 4; ii++)
                    dst4[ii] = make_float4(o[4*ii], o[4*ii+1], o[4*ii+2], o[4*ii+3]);
            }
        }
    }
}

// ---------------- edge pass 1: gate GEMM + m + sigma + segment reds + BN-e stats ----------------
// 128 threads, 128-edge tile, thread: 4 edges x 16 features.
__global__ __launch_bounds__(128) void k_edge1(
    const float* __restrict__ ef, const int* __restrict__ src,
    const int* __restrict__ dst,
    const float* __restrict__ Weg, const float* __restrict__ beg)
{
    extern __shared__ float sm[];
    float* W_sh   = sm;                 // 4096 floats
    float* ef_sh  = sm + 4096;          // 128*68 floats
    float* red_sh = sm + 4096 + 8704;   // 512 floats

    const int t = threadIdx.x;
    const int e0 = blockIdx.x * 128;
    const int fg = t & 3, g = t >> 2;
    const int j0 = fg * 16;

    {   // W
        float4* Wd = (float4*)W_sh;
        const float4* Wg = (const float4*)Weg;
        #pragma unroll
        for (int i = 0; i < 8; i++) Wd[t + i * 128] = Wg[t + i * 128];
    }
    {   // edge tile
        const float4* efg = (const float4*)ef;
        #pragma unroll
        for (int i = 0; i < 16; i++) {
            int idx = t + i * 128;
            int row = idx >> 4, c4 = idx & 15;
            ((float4*)(ef_sh + row * 68))[c4] = efg[(size_t)(e0 + row) * 16 + c4];
        }
    }
    __syncthreads();

    int se[4], de[4];
    #pragma unroll
    for (int q = 0; q < 4; q++) {
        int e = e0 + g + 32 * q;
        se[q] = src[e]; de[q] = dst[e];
    }

    u64 acc[4][8];
    {
        const float4* bg4 = (const float4*)(beg + j0);
        float4 b0 = bg4[0], b1 = bg4[1], b2 = bg4[2], b3 = bg4[3];
        u64 bb[8] = {pk2(b0.x,b0.y), pk2(b0.z,b0.w), pk2(b1.x,b1.y), pk2(b1.z,b1.w),
                     pk2(b2.x,b2.y), pk2(b2.z,b2.w), pk2(b3.x,b3.y), pk2(b3.z,b3.w)};
        #pragma unroll
        for (int q = 0; q < 4; q++)
            #pragma unroll
            for (int i = 0; i < 8; i++) acc[q][i] = bb[i];
    }

    const u64* W2 = (const u64*)W_sh;
    #pragma unroll 4
    for (int k = 0; k < 64; k++) {
        u64 w[8];
        #pragma unroll
        for (int i = 0; i < 8; i++) w[i] = W2[k * 32 + (j0 >> 1) + i];
        #pragma unroll
        for (int q = 0; q < 4; q++) {
            float ev = ef_sh[(g + 32 * q) * 68 + k];
            u64 e2 = pk2(ev, ev);
            #pragma unroll
            for (int i = 0; i < 8; i++) ffma2(acc[q][i], e2, w[i]);
        }
    }

    float s1[16], s2[16];
    #pragma unroll
    for (int i = 0; i < 16; i++) { s1[i] = 0.f; s2[i] = 0.f; }

    #pragma unroll
    for (int q = 0; q < 4; q++) {
        int e = e0 + g + 32 * q;
        float m[16];
        #pragma unroll
        for (int i = 0; i < 8; i++) upk2(acc[q][i], m[2 * i], m[2 * i + 1]);

        const float4* es4 = (const float4*)(g_esrc + (size_t)se[q] * 64 + j0);
        const float4* ed4 = (const float4*)(g_edst + (size_t)de[q] * 64 + j0);
        const float4* bh4 = (const float4*)(g_Bh   + (size_t)se[q] * 64 + j0);
        float4 esv[4], edv[4], bhv[4];
        #pragma unroll
        for (int i = 0; i < 4; i++) { esv[i] = es4[i]; edv[i] = ed4[i]; bhv[i] = bh4[i]; }
        const float* esf = (const float*)esv;
        const float* edf = (const float*)edv;
        const float* bhf = (const float*)bhv;

        float sig[16];
        #pragma unroll
        for (int i = 0; i < 16; i++) {
            m[i] += esf[i] + edf[i];
            sig[i] = sigmoidf_(m[i]);
            s1[i] += m[i];
            s2[i] = fmaf(m[i], m[i], s2[i]);
        }

        float* dnum = g_num + (size_t)de[q] * 64 + j0;
        float* dden = g_den + (size_t)de[q] * 64 + j0;
        #pragma unroll
        for (int ii = 0; ii < 4; ii++) {
            red4(dden + 4 * ii, make_float4(sig[4*ii], sig[4*ii+1], sig[4*ii+2], sig[4*ii+3]));
            red4(dnum + 4 * ii, make_float4(bhf[4*ii+0] * sig[4*ii+0],
                                            bhf[4*ii+1] * sig[4*ii+1],
                                            bhf[4*ii+2] * sig[4*ii+2],
                                            bhf[4*ii+3] * sig[4*ii+3]));
        }

        // store m as fp16 for pass 2
        u32 hm[8];
        #pragma unroll
        for (int i = 0; i < 8; i++) {
            __half2 h = __floats2half2_rn(m[2 * i], m[2 * i + 1]);
            hm[i] = *(u32*)&h;
        }
        uint4* mp = (uint4*)(g_m + (size_t)e * 64 + j0);
        mp[0] = make_uint4(hm[0], hm[1], hm[2], hm[3]);
        mp[1] = make_uint4(hm[4], hm[5], hm[6], hm[7]);
    }

    // BN-e stats: warp shfl reduce over the 8 lanes sharing fg (xor 4,8,16)
    #pragma unroll
    for (int off = 4; off < 32; off <<= 1) {
        #pragma unroll
        for (int i = 0; i < 16; i++) {
            s1[i] += __shfl_xor_sync(0xffffffffu, s1[i], off);
            s2[i] += __shfl_xor_sync(0xffffffffu, s2[i], off);
        }
    }
    int lane = t & 31, w = t >> 5;
    if (lane < 4) {
        #pragma unroll
        for (int i = 0; i < 16; i++) {
            red_sh[w * 128 + lane * 32 + i]      = s1[i];
            red_sh[w * 128 + lane * 32 + 16 + i] = s2[i];
        }
    }
    __syncthreads();
    {
        int fg2 = t >> 5, slot = t & 31;
        float v = red_sh[0 * 128 + fg2 * 32 + slot] + red_sh[1 * 128 + fg2 * 32 + slot]
                + red_sh[2 * 128 + fg2 * 32 + slot] + red_sh[3 * 128 + fg2 * 32 + slot];
        int j = fg2 * 16 + (slot & 15);
        atomicAdd(&g_stat[(slot < 16 ? 0 : 64) + j], v);
    }
}

// ---------------- node pass: x_pre = xs + num/(den+1e-6), BN-n stats ----------------
__global__ __launch_bounds__(256) void k_nodeA() {
    __shared__ float rsh[1024];
    const int t = threadIdx.x;
    const int j4 = t & 15, j = j4 * 4;
    const int r = blockIdx.x * 16 + (t >> 4);

    float4 nu = *(const float4*)(g_num + (size_t)r * 64 + j);
    float4 dn = *(const float4*)(g_den + (size_t)r * 64 + j);
    float4 xs = *(const float4*)(g_xs  + (size_t)r * 64 + j);
    float4 xp;
    xp.x = xs.x + __fdividef(nu.x, dn.x + 1e-6f);
    xp.y = xs.y + __fdividef(nu.y, dn.y + 1e-6f);
    xp.z = xs.z + __fdividef(nu.z, dn.z + 1e-6f);
    xp.w = xs.w + __fdividef(nu.w, dn.w + 1e-6f);
    *(float4*)(g_xpre + (size_t)r * 64 + j) = xp;

    float s1[4] = {xp.x, xp.y, xp.z, xp.w};
    float s2[4] = {xp.x * xp.x, xp.y * xp.y, xp.z * xp.z, xp.w * xp.w};
    #pragma unroll
    for (int i = 0; i < 4; i++) {
        s1[i] += __shfl_xor_sync(0xffffffffu, s1[i], 16);
        s2[i] += __shfl_xor_sync(0xffffffffu, s2[i], 16);
    }
    int lane = t & 31, w = t >> 5;
    if (lane < 16) {
        #pragma unroll
        for (int v = 0; v < 4; v++) {
            rsh[w * 128 + lane * 8 + v]     = s1[v];
            rsh[w * 128 + lane * 8 + 4 + v] = s2[v];
        }
    }
    __syncthreads();
    if (t < 128) {
        int jj4 = t >> 3, v = t & 7;
        float val = 0.f;
        #pragma unroll
        for (int w2 = 0; w2 < 8; w2++) val += rsh[w2 * 128 + jj4 * 8 + v];
        int feat = jj4 * 4 + (v & 3);
        atomicAdd(&g_stat[(v < 4 ? 128 : 192) + feat], val);
    }
}

// ---------------- finalize BN affine params ----------------
__global__ void k_bnfin(const float* __restrict__ gn, const float* __restrict__ btn,
                        const float* __restrict__ ge, const float* __restrict__ bte) {
    int t = threadIdx.x;
    if (t < 64) {
        float mean = g_stat[t] * (1.f / (float)EE);
        float var  = g_stat[64 + t] * (1.f / (float)EE) - mean * mean;
        float a = ge[t] * rsqrtf(var + 1e-5f);
        g_bn[t] = a;
        g_bn[64 + t] = bte[t] - mean * a;
    } else if (t < 128) {
        int j = t - 64;
        float mean = g_stat[128 + j] * (1.f / (float)NN);
        float var  = g_stat[192 + j] * (1.f / (float)NN) - mean * mean;
        float a = gn[j] * rsqrtf(var + 1e-5f);
        g_bn[128 + j] = a;
        g_bn[192 + j] = btn[j] - mean * a;
    }
}

// ---------------- node output: x = nf + silu(bn_n(x_pre)) ----------------
__global__ __launch_bounds__(256) void k_nodeOut(const float* __restrict__ nf,
                                                 float* __restrict__ out) {
    const int t = threadIdx.x;
    const int j = (t & 15) * 4;
    const int r = blockIdx.x * 16 + (t >> 4);
    float4 a  = *(const float4*)(g_bn + 128 + j);
    float4 b  = *(const float4*)(g_bn + 192 + j);
    float4 xp = *(const float4*)(g_xpre + (size_t)r * 64 + j);
    float4 nv = *(const float4*)(nf + (size_t)r * 64 + j);
    float4 o;
    o.x = nv.x + siluf_(a.x * xp.x + b.x);
    o.y = nv.y + siluf_(a.y * xp.y + b.y);
    o.z = nv.z + siluf_(a.z * xp.z + b.z);
    o.w = nv.w + siluf_(a.w * xp.w + b.w);
    *(float4*)(out + (size_t)r * 64 + j) = o;
}

// ---------------- edge output: y = ef + silu(bn_e(m)) ----------------
__global__ __launch_bounds__(256) void k_edge2(const float* __restrict__ ef,
                                               float* __restrict__ out) {
    size_t idx = (size_t)blockIdx.x * 256 + threadIdx.x;
    size_t e = idx >> 4;
    int j = (int)(idx & 15) * 4;
    u64 mv = *(const u64*)(g_m + e * 64 + j);
    __half2 h0 = ((__half2*)&mv)[0], h1 = ((__half2*)&mv)[1];
    float2 f0 = __half22float2(h0), f1 = __half22float2(h1);
    float4 a  = *(const float4*)(g_bn + j);
    float4 b  = *(const float4*)(g_bn + 64 + j);
    float4 ev = *(const float4*)(ef + e * 64 + j);
    float4 o;
    o.x = ev.x + siluf_(a.x * f0.x + b.x);
    o.y = ev.y + siluf_(a.y * f0.y + b.y);
    o.z = ev.z + siluf_(a.z * f1.x + b.z);
    o.w = ev.w + siluf_(a.w * f1.y + b.w);
    *(float4*)(out + (size_t)NN * 64 + e * 64 + j) = o;
}

// ---------------- launch ----------------
extern "C" void kernel_launch(void* const* d_in, const int* in_sizes, int n_in,
                              void* d_out, int out_size) {
    const float* nf  = (const float*)d_in[0];
    const float* ef  = (const float*)d_in[1];
    const int*   src = (const int*)d_in[2];
    const int*   dst = (const int*)d_in[3];
    const float *Wsg = (const float*)d_in[4],  *bsg = (const float*)d_in[5];
    const float *Wdg = (const float*)d_in[6],  *bdg = (const float*)d_in[7];
    const float *Weg = (const float*)d_in[8],  *beg = (const float*)d_in[9];
    const float *Wsu = (const float*)d_in[10], *bsu = (const float*)d_in[11];
    const float *Wdu = (const float*)d_in[12], *bdu = (const float*)d_in[13];
    const float *gn  = (const float*)d_in[14], *btn = (const float*)d_in[15];
    const float *ge  = (const float*)d_in[16], *bte = (const float*)d_in[17];
    float* out = (float*)d_out;

    cudaFuncSetAttribute(k_node_gemm, cudaFuncAttributeMaxDynamicSharedMemorySize, 51200);
    cudaFuncSetAttribute(k_edge1,     cudaFuncAttributeMaxDynamicSharedMemorySize, 53248);

    k_zero<<<12500, 256>>>();                                   // NN*D exactly
    k_node_gemm<<<391, 128, 51200>>>(nf, Wsg, bsg, Wdg, bdg, Wdu, bdu, Wsu, bsu);
    k_edge1<<<6250, 128, 53248>>>(ef, src, dst, Weg, beg);      // EE/128 exactly
    k_nodeA<<<3125, 256>>>();                                   // NN/16 exactly
    k_bnfin<<<1, 128>>>(gn, btn, ge, bte);
    k_nodeOut<<<3125, 256>>>(nf, out);
    k_edge2<<<50000, 256>>>(ef, out);                           // EE*16/256 exactly
}

// round 4
// speedup vs baseline: 1.1322x; 1.1322x over previous
#include <cuda_runtime.h>
#include <cuda_fp16.h>
#include <cstdint>

#define DEV __device__ __forceinline__
typedef unsigned long long u64;
typedef unsigned int u32;

static constexpr int NN = 50000;
static constexpr int EE = 800000;
static constexpr int D  = 64;

// ---------------- device scratch ----------------
__device__ float g_esrc[(size_t)NN * D];
__device__ float g_edst[(size_t)NN * D];
__device__ float g_Bh  [(size_t)NN * D];
__device__ float g_xs  [(size_t)NN * D];
__device__ float g_num [(size_t)NN * D];
__device__ float g_den [(size_t)NN * D];
__device__ float g_xpre[(size_t)NN * D];
__device__ __half g_m  [(size_t)EE * D];
// stats: [0:64) e_sum [64:128) e_sumsq [128:192) n_sum [192:256) n_sumsq
__device__ float g_stat[256];
// bn params: [0:64) a_e [64:128) b_e [128:192) a_n [192:256) b_n
__device__ float g_bn[256];

// ---------------- helpers ----------------
DEV u64 pk2(float lo, float hi) {
    u64 r; asm("mov.b64 %0,{%1,%2};" : "=l"(r) : "f"(lo), "f"(hi)); return r;
}
DEV void upk2(u64 v, float& lo, float& hi) {
    asm("mov.b64 {%0,%1},%2;" : "=f"(lo), "=f"(hi) : "l"(v));
}
DEV void ffma2(u64& d, u64 a, u64 b) {
    asm("fma.rn.f32x2 %0,%1,%2,%0;" : "+l"(d) : "l"(a), "l"(b));
}
DEV void red4(float* p, float4 v) {
    asm volatile("red.global.add.v4.f32 [%0],{%1,%2,%3,%4};"
                 :: "l"(p), "f"(v.x), "f"(v.y), "f"(v.z), "f"(v.w) : "memory");
}
DEV float sigmoidf_(float v) { return __fdividef(1.f, 1.f + __expf(-v)); }
DEV float siluf_(float v)    { return __fdividef(v,   1.f + __expf(-v)); }

// ---------------- zero accumulators (every replay) ----------------
__global__ void k_zero() {
    int i = blockIdx.x * blockDim.x + threadIdx.x;   // grid covers NN*D/4 exactly
    ((float4*)g_num)[i] = make_float4(0.f, 0.f, 0.f, 0.f);
    ((float4*)g_den)[i] = make_float4(0.f, 0.f, 0.f, 0.f);
    if (i < 256) g_stat[i] = 0.f;
}

// ---------------- node GEMMs: mi = blockIdx.y selects matrix ----------------
// 128 threads, 128-node tile. Lane layout: fg = t&15 owns features fg*4..fg*4+3,
// g = t>>4 owns nodes g+8q (q=0..15).
__global__ __launch_bounds__(128) void k_node_gemm(
    const float* __restrict__ nf,
    const float* __restrict__ Wsg, const float* __restrict__ bsg,
    const float* __restrict__ Wdg, const float* __restrict__ bdg,
    const float* __restrict__ Wdu, const float* __restrict__ bdu,
    const float* __restrict__ Wsu, const float* __restrict__ bsu)
{
    extern __shared__ float sm[];
    float* W_sh  = sm;          // 4096 floats
    float* nf_sh = sm + 4096;   // 128*68 floats

    const int t = threadIdx.x;
    const int fg = t & 15, g = t >> 4;
    const int j0 = fg * 4;
    const int n0 = blockIdx.x * 128;
    const int mi = blockIdx.y;

    const float* Wp = (mi == 0) ? Wsg : (mi == 1) ? Wdg : (mi == 2) ? Wdu : Wsu;
    const float* bp = (mi == 0) ? bsg : (mi == 1) ? bdg : (mi == 2) ? bdu : bsu;
    float*       op = (mi == 0) ? g_esrc : (mi == 1) ? g_edst : (mi == 2) ? g_Bh : g_xs;

    {   // W
        float4* Wd = (float4*)W_sh;
        const float4* Wg = (const float4*)Wp;
        #pragma unroll
        for (int i = 0; i < 8; i++) Wd[t + i * 128] = Wg[t + i * 128];
    }
    {   // node tile (padded stride 68)
        const float4* nfg = (const float4*)nf;
        #pragma unroll
        for (int i = 0; i < 16; i++) {
            int idx = t + i * 128;
            int row = idx >> 4, c4 = idx & 15;
            float4 v = (n0 + row < NN) ? nfg[(size_t)(n0 + row) * 16 + c4]
                                       : make_float4(0.f, 0.f, 0.f, 0.f);
            ((float4*)(nf_sh + row * 68))[c4] = v;
        }
    }
    __syncthreads();

    u64 acc[16][2];
    {
        float4 bg = *(const float4*)(bp + j0);
        u64 b0 = pk2(bg.x, bg.y), b1 = pk2(bg.z, bg.w);
        #pragma unroll
        for (int q = 0; q < 16; q++) { acc[q][0] = b0; acc[q][1] = b1; }
    }

    const u64* W2 = (const u64*)W_sh;
    #pragma unroll 4
    for (int k4 = 0; k4 < 16; k4++) {
        u64 w[4][2];
        #pragma unroll
        for (int kk = 0; kk < 4; kk++) {
            w[kk][0] = W2[(k4 * 4 + kk) * 32 + fg * 2];
            w[kk][1] = W2[(k4 * 4 + kk) * 32 + fg * 2 + 1];
        }
        #pragma unroll
        for (int q = 0; q < 16; q++) {
            float4 ev = *(const float4*)(nf_sh + (g + 8 * q) * 68 + k4 * 4);
            u64 e0p = pk2(ev.x, ev.x), e1p = pk2(ev.y, ev.y);
            u64 e2p = pk2(ev.z, ev.z), e3p = pk2(ev.w, ev.w);
            ffma2(acc[q][0], e0p, w[0][0]); ffma2(acc[q][1], e0p, w[0][1]);
            ffma2(acc[q][0], e1p, w[1][0]); ffma2(acc[q][1], e1p, w[1][1]);
            ffma2(acc[q][0], e2p, w[2][0]); ffma2(acc[q][1], e2p, w[2][1]);
            ffma2(acc[q][0], e3p, w[3][0]); ffma2(acc[q][1], e3p, w[3][1]);
        }
    }

    #pragma unroll
    for (int q = 0; q < 16; q++) {
        int n = n0 + g + 8 * q;
        if (n < NN) {
            float o0, o1, o2, o3;
            upk2(acc[q][0], o0, o1); upk2(acc[q][1], o2, o3);
            *(float4*)(op + (size_t)n * 64 + j0) = make_float4(o0, o1, o2, o3);
        }
    }
}

// ---------------- edge pass 1 ----------------
// 128 threads, 128-edge tile. fg = t&15 (features fg*4..+3), g = t>>4, edges g+8q.
__global__ __launch_bounds__(128) void k_edge1(
    const float* __restrict__ ef, const int* __restrict__ src,
    const int* __restrict__ dst,
    const float* __restrict__ Weg, const float* __restrict__ beg)
{
    extern __shared__ float sm[];
    float* W_sh   = sm;                 // 4096 floats
    float* ef_sh  = sm + 4096;          // 8704 floats
    int*   s_src  = (int*)(sm + 12800); // 128
    int*   s_dst  = (int*)(sm + 12928); // 128
    float* red_sh = sm + 13056;         // 512 floats

    const int t = threadIdx.x;
    const int e0 = blockIdx.x * 128;
    const int fg = t & 15, g = t >> 4;
    const int j0 = fg * 4;

    s_src[t] = src[e0 + t];
    s_dst[t] = dst[e0 + t];
    {   // W
        float4* Wd = (float4*)W_sh;
        const float4* Wg = (const float4*)Weg;
        #pragma unroll
        for (int i = 0; i < 8; i++) Wd[t + i * 128] = Wg[t + i * 128];
    }
    {   // edge tile
        const float4* efg = (const float4*)ef;
        #pragma unroll
        for (int i = 0; i < 16; i++) {
            int idx = t + i * 128;
            int row = idx >> 4, c4 = idx & 15;
            ((float4*)(ef_sh + row * 68))[c4] = efg[(size_t)(e0 + row) * 16 + c4];
        }
    }
    __syncthreads();

    u64 acc[16][2];
    {
        float4 bg = *(const float4*)(beg + j0);
        u64 b0 = pk2(bg.x, bg.y), b1 = pk2(bg.z, bg.w);
        #pragma unroll
        for (int q = 0; q < 16; q++) { acc[q][0] = b0; acc[q][1] = b1; }
    }

    const u64* W2 = (const u64*)W_sh;
    #pragma unroll 4
    for (int k4 = 0; k4 < 16; k4++) {
        u64 w[4][2];
        #pragma unroll
        for (int kk = 0; kk < 4; kk++) {
            w[kk][0] = W2[(k4 * 4 + kk) * 32 + fg * 2];
            w[kk][1] = W2[(k4 * 4 + kk) * 32 + fg * 2 + 1];
        }
        #pragma unroll
        for (int q = 0; q < 16; q++) {
            float4 ev = *(const float4*)(ef_sh + (g + 8 * q) * 68 + k4 * 4);
            u64 e0p = pk2(ev.x, ev.x), e1p = pk2(ev.y, ev.y);
            u64 e2p = pk2(ev.z, ev.z), e3p = pk2(ev.w, ev.w);
            ffma2(acc[q][0], e0p, w[0][0]); ffma2(acc[q][1], e0p, w[0][1]);
            ffma2(acc[q][0], e1p, w[1][0]); ffma2(acc[q][1], e1p, w[1][1]);
            ffma2(acc[q][0], e2p, w[2][0]); ffma2(acc[q][1], e2p, w[2][1]);
            ffma2(acc[q][0], e3p, w[3][0]); ffma2(acc[q][1], e3p, w[3][1]);
        }
    }

    float s1[4] = {0.f, 0.f, 0.f, 0.f};
    float s2[4] = {0.f, 0.f, 0.f, 0.f};

    // epilogue in chunks of 4 edges for MLP
    #pragma unroll
    for (int qq = 0; qq < 16; qq += 4) {
        float4 es[4], ed[4], bh[4];
        int de_[4];
        #pragma unroll
        for (int u = 0; u < 4; u++) {
            int q = qq + u;
            int sv = s_src[g + 8 * q];
            int dv = s_dst[g + 8 * q];
            de_[u] = dv;
            es[u] = *(const float4*)(g_esrc + (size_t)sv * 64 + j0);
            ed[u] = *(const float4*)(g_edst + (size_t)dv * 64 + j0);
            bh[u] = *(const float4*)(g_Bh   + (size_t)sv * 64 + j0);
        }
        #pragma unroll
        for (int u = 0; u < 4; u++) {
            int q = qq + u;
            int e = e0 + g + 8 * q;
            float m0, m1, m2, m3;
            upk2(acc[q][0], m0, m1); upk2(acc[q][1], m2, m3);
            m0 += es[u].x + ed[u].x;
            m1 += es[u].y + ed[u].y;
            m2 += es[u].z + ed[u].z;
            m3 += es[u].w + ed[u].w;
            float g0 = sigmoidf_(m0), g1 = sigmoidf_(m1);
            float g2 = sigmoidf_(m2), g3 = sigmoidf_(m3);
            s1[0] += m0; s1[1] += m1; s1[2] += m2; s1[3] += m3;
            s2[0] = fmaf(m0, m0, s2[0]); s2[1] = fmaf(m1, m1, s2[1]);
            s2[2] = fmaf(m2, m2, s2[2]); s2[3] = fmaf(m3, m3, s2[3]);

            float* base = g_den + (size_t)de_[u] * 64 + j0;
            red4(base, make_float4(g0, g1, g2, g3));
            float* basen = g_num + (size_t)de_[u] * 64 + j0;
            red4(basen, make_float4(bh[u].x * g0, bh[u].y * g1,
                                    bh[u].z * g2, bh[u].w * g3));

            __half2 h0 = __floats2half2_rn(m0, m1);
            __half2 h1 = __floats2half2_rn(m2, m3);
            u64 hm = pk2(__uint_as_float(*(u32*)&h0), __uint_as_float(*(u32*)&h1));
            *(u64*)(g_m + (size_t)e * 64 + j0) = hm;
        }
    }

    // BN-e stats: reduce lanes sharing fg (xor 16), then across 4 warps
    #pragma unroll
    for (int i = 0; i < 4; i++) {
        s1[i] += __shfl_xor_sync(0xffffffffu, s1[i], 16);
        s2[i] += __shfl_xor_sync(0xffffffffu, s2[i], 16);
    }
    int lane = t & 31, w = t >> 5;
    if (lane < 16) {
        #pragma unroll
        for (int i = 0; i < 4; i++) {
            red_sh[w * 128 + lane * 8 + i]     = s1[i];
            red_sh[w * 128 + lane * 8 + 4 + i] = s2[i];
        }
    }
    __syncthreads();
    {
        int fg2 = t >> 3;   // 0..15
        int v = t & 7;      // 0..3 -> s1, 4..7 -> s2
        float val = red_sh[0 * 128 + fg2 * 8 + v] + red_sh[1 * 128 + fg2 * 8 + v]
                  + red_sh[2 * 128 + fg2 * 8 + v] + red_sh[3 * 128 + fg2 * 8 + v];
        int feat = fg2 * 4 + (v & 3);
        atomicAdd(&g_stat[(v < 4 ? 0 : 64) + feat], val);
    }
}

// ---------------- node pass: x_pre = xs + num/(den+1e-6), BN-n stats ----------------
__global__ __launch_bounds__(256) void k_nodeA() {
    __shared__ float rsh[1024];
    const int t = threadIdx.x;
    const int j = (t & 15) * 4;
    const int r0 = blockIdx.x * 32 + (t >> 4);
    const int r1 = r0 + 16;

    float s1[4] = {0.f, 0.f, 0.f, 0.f};
    float s2[4] = {0.f, 0.f, 0.f, 0.f};

    {
        float4 nu = *(const float4*)(g_num + (size_t)r0 * 64 + j);
        float4 dn = *(const float4*)(g_den + (size_t)r0 * 64 + j);
        float4 xs = *(const float4*)(g_xs  + (size_t)r0 * 64 + j);
        float4 xp;
        xp.x = xs.x + __fdividef(nu.x, dn.x + 1e-6f);
        xp.y = xs.y + __fdividef(nu.y, dn.y + 1e-6f);
        xp.z = xs.z + __fdividef(nu.z, dn.z + 1e-6f);
        xp.w = xs.w + __fdividef(nu.w, dn.w + 1e-6f);
        *(float4*)(g_xpre + (size_t)r0 * 64 + j) = xp;
        s1[0] += xp.x; s1[1] += xp.y; s1[2] += xp.z; s1[3] += xp.w;
        s2[0] = fmaf(xp.x, xp.x, s2[0]); s2[1] = fmaf(xp.y, xp.y, s2[1]);
        s2[2] = fmaf(xp.z, xp.z, s2[2]); s2[3] = fmaf(xp.w, xp.w, s2[3]);
    }
    if (r1 < NN) {
        float4 nu = *(const float4*)(g_num + (size_t)r1 * 64 + j);
        float4 dn = *(const float4*)(g_den + (size_t)r1 * 64 + j);
        float4 xs = *(const float4*)(g_xs  + (size_t)r1 * 64 + j);
        float4 xp;
        xp.x = xs.x + __fdividef(nu.x, dn.x + 1e-6f);
        xp.y = xs.y + __fdividef(nu.y, dn.y + 1e-6f);
        xp.z = xs.z + __fdividef(nu.z, dn.z + 1e-6f);
        xp.w = xs.w + __fdividef(nu.w, dn.w + 1e-6f);
        *(float4*)(g_xpre + (size_t)r1 * 64 + j) = xp;
        s1[0] += xp.x; s1[1] += xp.y; s1[2] += xp.z; s1[3] += xp.w;
        s2[0] = fmaf(xp.x, xp.x, s2[0]); s2[1] = fmaf(xp.y, xp.y, s2[1]);
        s2[2] = fmaf(xp.z, xp.z, s2[2]); s2[3] = fmaf(xp.w, xp.w, s2[3]);
    }

    #pragma unroll
    for (int i = 0; i < 4; i++) {
        s1[i] += __shfl_xor_sync(0xffffffffu, s1[i], 16);
        s2[i] += __shfl_xor_sync(0xffffffffu, s2[i], 16);
    }
    int lane = t & 31, w = t >> 5;
    if (lane < 16) {
        #pragma unroll
        for (int v = 0; v < 4; v++) {
            rsh[w * 128 + lane * 8 + v]     = s1[v];
            rsh[w * 128 + lane * 8 + 4 + v] = s2[v];
        }
    }
    __syncthreads();
    if (t < 128) {
        int jj4 = t >> 3, v = t & 7;
        float val = 0.f;
        #pragma unroll
        for (int w2 = 0; w2 < 8; w2++) val += rsh[w2 * 128 + jj4 * 8 + v];
        int feat = jj4 * 4 + (v & 3);
        atomicAdd(&g_stat[(v < 4 ? 128 : 192) + feat], val);
    }
}

// ---------------- finalize BN affine params ----------------
__global__ void k_bnfin(const float* __restrict__ gn, const float* __restrict__ btn,
                        const float* __restrict__ ge, const float* __restrict__ bte) {
    int t = threadIdx.x;
    if (t < 64) {
        float mean = g_stat[t] * (1.f / (float)EE);
        float var  = g_stat[64 + t] * (1.f / (float)EE) - mean * mean;
        float a = ge[t] * rsqrtf(var + 1e-5f);
        g_bn[t] = a;
        g_bn[64 + t] = bte[t] - mean * a;
    } else if (t < 128) {
        int j = t - 64;
        float mean = g_stat[128 + j] * (1.f / (float)NN);
        float var  = g_stat[192 + j] * (1.f / (float)NN) - mean * mean;
        float a = gn[j] * rsqrtf(var + 1e-5f);
        g_bn[128 + j] = a;
        g_bn[192 + j] = btn[j] - mean * a;
    }
}

// ---------------- node output: x = nf + silu(bn_n(x_pre)) ----------------
__global__ __launch_bounds__(256) void k_nodeOut(const float* __restrict__ nf,
                                                 float* __restrict__ out) {
    const int t = threadIdx.x;
    const int j = (t & 15) * 4;
    const int r = blockIdx.x * 16 + (t >> 4);
    float4 a  = *(const float4*)(g_bn + 128 + j);
    float4 b  = *(const float4*)(g_bn + 192 + j);
    float4 xp = *(const float4*)(g_xpre + (size_t)r * 64 + j);
    float4 nv = *(const float4*)(nf + (size_t)r * 64 + j);
    float4 o;
    o.x = nv.x + siluf_(a.x * xp.x + b.x);
    o.y = nv.y + siluf_(a.y * xp.y + b.y);
    o.z = nv.z + siluf_(a.z * xp.z + b.z);
    o.w = nv.w + siluf_(a.w * xp.w + b.w);
    *(float4*)(out + (size_t)r * 64 + j) = o;
}

// ---------------- edge output: y = ef + silu(bn_e(m)), 8 floats/thread ----------------
__global__ __launch_bounds__(256) void k_edge2(const float* __restrict__ ef,
                                               float* __restrict__ out) {
    size_t idx = (size_t)blockIdx.x * 256 + threadIdx.x;   // EE*8 threads
    size_t e = idx >> 3;
    int j = (int)(idx & 7) * 8;

    uint4 mv = *(const uint4*)(g_m + e * 64 + j);
    float2 f0 = __half22float2(*(__half2*)&mv.x);
    float2 f1 = __half22float2(*(__half2*)&mv.y);
    float2 f2 = __half22float2(*(__half2*)&mv.z);
    float2 f3 = __half22float2(*(__half2*)&mv.w);

    float4 a0 = *(const float4*)(g_bn + j);
    float4 a1 = *(const float4*)(g_bn + j + 4);
    float4 b0 = *(const float4*)(g_bn + 64 + j);
    float4 b1 = *(const float4*)(g_bn + 64 + j + 4);

    const float4* ev = (const float4*)(ef + e * 64 + j);
    float4 e0 = ev[0], e1 = ev[1];

    float4 o0, o1;
    o0.x = e0.x + siluf_(a0.x * f0.x + b0.x);
    o0.y = e0.y + siluf_(a0.y * f0.y + b0.y);
    o0.z = e0.z + siluf_(a0.z * f1.x + b0.z);
    o0.w = e0.w + siluf_(a0.w * f1.y + b0.w);
    o1.x = e1.x + siluf_(a1.x * f2.x + b1.x);
    o1.y = e1.y + siluf_(a1.y * f2.y + b1.y);
    o1.z = e1.z + siluf_(a1.z * f3.x + b1.z);
    o1.w = e1.w + siluf_(a1.w * f3.y + b1.w);

    float4* op = (float4*)(out + (size_t)NN * 64 + e * 64 + j);
    op[0] = o0; op[1] = o1;
}

// ---------------- launch ----------------
extern "C" void kernel_launch(void* const* d_in, const int* in_sizes, int n_in,
                              void* d_out, int out_size) {
    const float* nf  = (const float*)d_in[0];
    const float* ef  = (const float*)d_in[1];
    const int*   src = (const int*)d_in[2];
    const int*   dst = (const int*)d_in[3];
    const float *Wsg = (const float*)d_in[4],  *bsg = (const float*)d_in[5];
    const float *Wdg = (const float*)d_in[6],  *bdg = (const float*)d_in[7];
    const float *Weg = (const float*)d_in[8],  *beg = (const float*)d_in[9];
    const float *Wsu = (const float*)d_in[10], *bsu = (const float*)d_in[11];
    const float *Wdu = (const float*)d_in[12], *bdu = (const float*)d_in[13];
    const float *gn  = (const float*)d_in[14], *btn = (const float*)d_in[15];
    const float *ge  = (const float*)d_in[16], *bte = (const float*)d_in[17];
    float* out = (float*)d_out;

    cudaFuncSetAttribute(k_node_gemm, cudaFuncAttributeMaxDynamicSharedMemorySize, 51200);
    cudaFuncSetAttribute(k_edge1,     cudaFuncAttributeMaxDynamicSharedMemorySize, 54272);

    k_zero<<<3125, 256>>>();                                    // NN*D/4 exactly
    k_node_gemm<<<dim3(391, 4), 128, 51200>>>(nf, Wsg, bsg, Wdg, bdg, Wdu, bdu, Wsu, bsu);
    k_edge1<<<6250, 128, 54272>>>(ef, src, dst, Weg, beg);      // EE/128 exactly
    k_nodeA<<<1563, 256>>>();                                   // ceil(NN/32)
    k_bnfin<<<1, 128>>>(gn, btn, ge, bte);
    k_nodeOut<<<3125, 256>>>(nf, out);
    k_edge2<<<25000, 256>>>(ef, out);                           // EE*8/256 exactly
}